// round 13
// baseline (speedup 1.0000x reference)
#include <cuda_runtime.h>
#include <cuda_fp16.h>
#include <cstdint>
#include <cfloat>

#define N_VEC  16384
#define VOCAB  4096
#define C_DIM  256

#define SLK    0.05f     // fp32 scale/round slack (int dot itself is exact)

// ---------------------------------------------------------------------------
__device__ float  g_hflat[N_VEC * C_DIM];     // h transposed (N,C) fp32
__device__ signed char g_A8[N_VEC * C_DIM];   // int8 quantized x rows
__device__ signed char g_B8[VOCAB * C_DIM];   // int8 quantized codebook
__device__ float  g_halfnorm[VOCAB];          // 0.5*||e||^2 (rescore/loss)
__device__ alignas(16) float4 g_cb4[VOCAB];   // (hn, ||e||+ree, ree, se)
__device__ alignas(16) float4 g_rowp[N_VEC];  // (sx, ||x||+rex, rex, 0)
__device__ float  g_bestscore[N_VEC];
__device__ int    g_bestidx[N_VEC];
__device__ float  g_partial[4096];

// ---------------------------------------------------------------------------
__device__ __forceinline__ uint32_t smem_u32(const void* p) {
    uint32_t a;
    asm("{ .reg .u64 t; cvta.to.shared.u64 t, %1; cvt.u32.u64 %0, t; }"
        : "=r"(a) : "l"(p));
    return a;
}
__device__ __forceinline__ unsigned fmap(float f) {
    unsigned u = __float_as_uint(f);
    return u ^ ((unsigned)((int)u >> 31) | 0x80000000u);
}
#define CP_ASYNC16(saddr, gptr) \
    asm volatile("cp.async.cg.shared.global [%0], [%1], 16;" \
                 :: "r"(saddr), "l"(gptr) : "memory")
#define CP_COMMIT() asm volatile("cp.async.commit_group;" ::: "memory")
#define CP_WAIT2()  asm volatile("cp.async.wait_group 2;" ::: "memory")
#define CP_WAIT1()  asm volatile("cp.async.wait_group 1;" ::: "memory")
#define CP_WAIT0()  asm volatile("cp.async.wait_group 0;" ::: "memory")

#define PAIR_BAR(id) \
    asm volatile("bar.sync %0, 64;" :: "r"(id) : "memory")

// int8 IMMA: 16x8x32, s32 accumulate
#define MMA16832(c, a, b) \
    asm volatile( \
        "mma.sync.aligned.m16n8k32.row.col.s32.s8.s8.s32 " \
        "{%0,%1,%2,%3}, {%4,%5,%6,%7}, {%8,%9}, {%0,%1,%2,%3};" \
        : "+r"((c)[0]), "+r"((c)[1]), "+r"((c)[2]), "+r"((c)[3]) \
        : "r"((a)[0]), "r"((a)[1]), "r"((a)[2]), "r"((a)[3]), \
          "r"((b)[0]), "r"((b)[1]))

#define LDSM_X4(r0, r1, r2, r3, addr) \
    asm volatile("ldmatrix.sync.aligned.m8n8.x4.shared.b16 {%0,%1,%2,%3}, [%4];" \
                 : "=r"(r0), "=r"(r1), "=r"(r2), "=r"(r3) : "r"(addr))

// ---------------------------------------------------------------------------
// transpose h (B,C,H,W)->(N,C) fp32 + fused sum(h^2) partial
__global__ void prep_h_kernel(const float* __restrict__ h) {
    __shared__ float tile[32][33];
    __shared__ float rsm[8];
    int b = blockIdx.z, ct = blockIdx.y, st = blockIdx.x;
    int c0 = ct * 32, s0 = st * 32;
    int tx = threadIdx.x, ty = threadIdx.y;
    int t = ty * 32 + tx;

    const float* src = h + ((size_t)b * C_DIM + c0) * 1024 + s0;
    float sq = 0.f;
    #pragma unroll
    for (int i = 0; i < 32; i += 8) {
        float v = src[(size_t)(ty + i) * 1024 + tx];
        tile[ty + i][tx] = v;
        sq = fmaf(v, v, sq);
    }
    __syncthreads();
    size_t rowbase = (size_t)b * 1024 + s0;
    #pragma unroll
    for (int i = 0; i < 32; i += 8)
        g_hflat[(rowbase + ty + i) * C_DIM + c0 + tx] = tile[tx][ty + i];
    #pragma unroll
    for (int o = 16; o > 0; o >>= 1) sq += __shfl_down_sync(0xFFFFFFFFu, sq, o);
    if ((t & 31) == 0) rsm[t >> 5] = sq;
    __syncthreads();
    if (t == 0) {
        float tot = 0.f;
        #pragma unroll
        for (int i = 0; i < 8; i++) tot += rsm[i];
        g_partial[(b * 8 + ct) * 32 + st] = tot;
    }
}

// quantize x rows to int8 + row params (warp per row)
__global__ void prep_hq_kernel() {
    int w = threadIdx.x >> 5, lane = threadIdx.x & 31;
    int r = blockIdx.x * 8 + w;
    const float* xp = g_hflat + (size_t)r * C_DIM;
    float v[8];
    float4 a4 = *reinterpret_cast<const float4*>(xp + lane * 8);
    float4 b4 = *reinterpret_cast<const float4*>(xp + lane * 8 + 4);
    v[0] = a4.x; v[1] = a4.y; v[2] = a4.z; v[3] = a4.w;
    v[4] = b4.x; v[5] = b4.y; v[6] = b4.z; v[7] = b4.w;

    float amax = 0.f;
    #pragma unroll
    for (int j = 0; j < 8; j++) amax = fmaxf(amax, fabsf(v[j]));
    #pragma unroll
    for (int o = 16; o > 0; o >>= 1)
        amax = fmaxf(amax, __shfl_xor_sync(0xFFFFFFFFu, amax, o));
    float sx = fmaxf(amax, 1e-20f) * (1.f / 127.f);
    float inv = 1.f / sx;

    int q[8];
    float xn2 = 0.f, rx2 = 0.f;
    #pragma unroll
    for (int j = 0; j < 8; j++) {
        int qq = (int)rintf(v[j] * inv);
        qq = max(-127, min(127, qq));
        q[j] = qq;
        float res = v[j] - sx * (float)qq;
        xn2 = fmaf(v[j], v[j], xn2);
        rx2 = fmaf(res, res, rx2);
    }
    unsigned lo = (q[0] & 255) | ((q[1] & 255) << 8) | ((q[2] & 255) << 16)
                | ((unsigned)(q[3] & 255) << 24);
    unsigned hi = (q[4] & 255) | ((q[5] & 255) << 8) | ((q[6] & 255) << 16)
                | ((unsigned)(q[7] & 255) << 24);
    reinterpret_cast<uint2*>(g_A8 + (size_t)r * C_DIM)[lane] = make_uint2(lo, hi);

    #pragma unroll
    for (int o = 16; o > 0; o >>= 1) {
        xn2 += __shfl_xor_sync(0xFFFFFFFFu, xn2, o);
        rx2 += __shfl_xor_sync(0xFFFFFFFFu, rx2, o);
    }
    if (lane == 0) {
        float rex = sqrtf(rx2);
        g_rowp[r] = make_float4(sx, sqrtf(xn2) + rex, rex, 0.f);
    }
}

// embedding: int8 quantize + exact norms/residuals (block per row)
__global__ void prep_emb_kernel(const float* __restrict__ emb) {
    __shared__ float sm1[8], sm2[8];
    __shared__ float s_se;
    int v = blockIdx.x, t = threadIdx.x;
    float x = emb[v * C_DIM + t];

    float am = fabsf(x);
    #pragma unroll
    for (int o = 16; o > 0; o >>= 1)
        am = fmaxf(am, __shfl_xor_sync(0xFFFFFFFFu, am, o));
    if ((t & 31) == 0) sm1[t >> 5] = am;
    __syncthreads();
    if (t == 0) {
        float m = 0.f;
        #pragma unroll
        for (int i = 0; i < 8; i++) m = fmaxf(m, sm1[i]);
        s_se = fmaxf(m, 1e-20f) * (1.f / 127.f);
    }
    __syncthreads();
    float se = s_se;
    int q = (int)rintf(x / se);
    q = max(-127, min(127, q));
    g_B8[v * C_DIM + t] = (signed char)q;
    float res = x - se * (float)q;

    float sxx = x * x, srr = res * res;
    #pragma unroll
    for (int o = 16; o > 0; o >>= 1) {
        sxx += __shfl_xor_sync(0xFFFFFFFFu, sxx, o);
        srr += __shfl_xor_sync(0xFFFFFFFFu, srr, o);
    }
    if ((t & 31) == 0) { sm1[t >> 5] = sxx; sm2[t >> 5] = srr; }
    __syncthreads();
    if (t == 0) {
        float exx = 0.f, err = 0.f;
        #pragma unroll
        for (int i = 0; i < 8; i++) { exx += sm1[i]; err += sm2[i]; }
        float en = sqrtf(exx), ree = sqrtf(err);
        g_halfnorm[v] = 0.5f * exx;
        g_cb4[v] = make_float4(0.5f * exx, en + ree, ree, se);
    }
}

// ---------------------------------------------------------------------------
// Fused int8 IMMA GEMM (pair-private pipeline) + margin filter + exact rescore.
// 256 CTAs (M tile 64) x 256 threads (wm=w&1, wn=w>>1). Warp tile 32x32.
// v-tile N=128 (32 tiles); K chunks of 128 int8 bytes (2 per v-tile). NC=64.
#define MTILE 64
#define LDAB  272        // A row bytes (256+16); mod 128 = 16 -> LDSM ok
#define LDBB  144        // B chunk row bytes (128+16); mod 128 = 16 -> LDSM ok
#define BSTAGE (128 * LDBB)      // 18432
#define CAP   64
#define NC    64
#define OFF_A    0                        // 64*272 = 17408
#define OFF_B    17408                    // 4 stages * 18432 = 73728
#define OFF_HNE  91136                    // 4 slots * 128 * 16B = 8192
#define OFF_ML   99328                    // 64 u32 (+pad)
#define OFF_CNT  99584                    // 64 ints (+pad)
#define OFF_CAND 99840                    // 64*64 u16 = 8192
#define SMEM_P1  108032

__global__ __launch_bounds__(256, 2) void pass1_kernel(const float* __restrict__ emb) {
    extern __shared__ char smem[];
    const uint32_t sb = smem_u32(smem);
    unsigned* ML  = reinterpret_cast<unsigned*>(smem + OFF_ML);
    int*      CNT = reinterpret_cast<int*>(smem + OFF_CNT);
    unsigned short* CAND = reinterpret_cast<unsigned short*>(smem + OFF_CAND);

    const int tid = threadIdx.x;
    const int w = tid >> 5, lane = tid & 31;
    const int wm = w & 1, wn = w >> 1;
    const int barid = wn + 1;
    const int m0 = blockIdx.x * MTILE;
    const int lg = lane >> 2;
    const int lq = lane & 3;

    if (tid < 64) { ML[tid] = 0u; CNT[tid] = 0; }

    // ldmatrix lane addresses (bytes)
    const uint32_t aLane = (uint32_t)((lane & 15) * LDAB + (lane >> 4) * 16);
    const uint32_t aBase0 = sb + OFF_A + (uint32_t)(wm * 32 * LDAB) + aLane;
    const uint32_t bLane = (uint32_t)(
        (((lane & 7) | ((lane >> 4) << 3)) * LDBB) + ((lane >> 3) & 1) * 16);
    const uint32_t bWarp = (uint32_t)(wn * 32 * LDBB) + bLane;

    // per-thread row params (4 rows this thread filters)
    const int rbase = wm * 32 + lg;
    float4 rp[2][2];
    #pragma unroll
    for (int mf = 0; mf < 2; mf++)
        #pragma unroll
        for (int hh = 0; hh < 2; hh++)
            rp[mf][hh] = __ldg(&g_rowp[m0 + rbase + mf * 16 + hh * 8]);

    // A tile loader: 64 rows x 256B, 4x16B per thread
    {
        const int ar = tid >> 2, as = (tid & 3) * 4;
        const char* asrc = reinterpret_cast<const char*>(g_A8) + (size_t)(m0 + ar) * C_DIM;
        #pragma unroll
        for (int j = 0; j < 4; j++)
            CP_ASYNC16(sb + OFF_A + (uint32_t)(ar * LDAB + (as + j) * 16),
                       asrc + (as + j) * 16);
        CP_COMMIT();
    }

    // pair-private B loader: warp loads 16 rows x 128B of pair's 32-row slice
    const int prow = wn * 32 + wm * 16 + (lane >> 1);
    const int pseg = (lane & 1) * 4;
    const uint32_t pdst = (uint32_t)(prow * LDBB);

    // chunk c: vt = c>>1, kc = c&1. HNE slot = vt&3 (written at c even, i.e.
    // during iter c-3 (odd) whose epilogue reads slot (vt-2)&3 — disjoint).
    #define PREFETCH(c) do {                                                      \
        const int _vt = (c) >> 1, _kc = (c) & 1;                                  \
        const uint32_t _dst = sb + OFF_B + (uint32_t)(((c) & 3) * BSTAGE) + pdst; \
        const char* _src = reinterpret_cast<const char*>(g_B8)                    \
                         + (size_t)(_vt * 128 + prow) * C_DIM + _kc * 128;        \
        _Pragma("unroll")                                                         \
        for (int _j = 0; _j < 4; _j++)                                            \
            CP_ASYNC16(_dst + (uint32_t)((pseg + _j) * 16), _src + (pseg + _j) * 16); \
        if (_kc == 0 && wm == 0) {                                                \
            CP_ASYNC16(sb + OFF_HNE + (uint32_t)((_vt & 3) * 2048 + (wn * 32 + lane) * 16), \
                       g_cb4 + _vt * 128 + wn * 32 + lane);                       \
        }                                                                         \
        CP_COMMIT();                                                              \
    } while (0)

    PREFETCH(0);
    PREFETCH(1);
    PREFETCH(2);
    CP_WAIT2();        // A group + chunk 0 complete (per thread)
    __syncthreads();   // only block barrier before mainloop

    int acc[2][4][4];

    #pragma unroll 2
    for (int i = 0; i < NC; i++) {
        if (i < NC - 2)       CP_WAIT2();
        else if (i == NC - 2) CP_WAIT1();
        else                  CP_WAIT0();
        // partner finished iter i-1 reads of stage (i+3)&3 -> safe to refill
        PAIR_BAR(barid);

        if (i + 3 < NC) PREFETCH(i + 3);

        const int kc = i & 1;
        const int vt = i >> 1;

        if (kc == 0) {
            #pragma unroll
            for (int mf = 0; mf < 2; mf++)
                #pragma unroll
                for (int nf = 0; nf < 4; nf++)
                    #pragma unroll
                    for (int q = 0; q < 4; q++) acc[mf][nf][q] = 0;
        }

        const uint32_t bStage = sb + OFF_B + (uint32_t)((i & 3) * BSTAGE) + bWarp;
        const uint32_t aK = (uint32_t)(kc * 128);

        #pragma unroll
        for (int ks = 0; ks < 4; ks++) {        // 32 int8 per k-step
            uint32_t a[2][4], b[4][2];
            const uint32_t ka = aK + (uint32_t)(ks * 32);
            const uint32_t kb = (uint32_t)(ks * 32);
            LDSM_X4(a[0][0], a[0][1], a[0][2], a[0][3], aBase0 + ka);
            LDSM_X4(a[1][0], a[1][1], a[1][2], a[1][3],
                    aBase0 + (uint32_t)(16 * LDAB) + ka);
            LDSM_X4(b[0][0], b[0][1], b[1][0], b[1][1], bStage + kb);
            LDSM_X4(b[2][0], b[2][1], b[3][0], b[3][1],
                    bStage + (uint32_t)(16 * LDBB) + kb);
            #pragma unroll
            for (int mf = 0; mf < 2; mf++)
                #pragma unroll
                for (int nf = 0; nf < 4; nf++)
                    MMA16832(acc[mf][nf], a[mf], b[nf]);
        }

        if (kc == 1) {
            // ---- epilogue for v-tile [vt*128, +128) ----
            const float4* HNE = reinterpret_cast<const float4*>(
                smem + OFF_HNE + (vt & 3) * 2048);
            const int v0 = vt << 7;
            #pragma unroll
            for (int mf = 0; mf < 2; mf++) {
                #pragma unroll
                for (int hh = 0; hh < 2; hh++) {
                    const int row = rbase + mf * 16 + hh * 8;
                    const float sx  = rp[mf][hh].x;
                    const float x1  = rp[mf][hh].y;   // ||x|| + rex
                    const float rex = rp[mf][hh].z;
                    float lowmax = -FLT_MAX;
                    float ub[4][2];
                    #pragma unroll
                    for (int nf = 0; nf < 4; nf++) {
                        const int col = wn * 32 + nf * 8 + lq * 2;
                        float4 qa = HNE[col];
                        float4 qb = HNE[col + 1];
                        // s = sx*se*acc - hn ; m = x1*ree + rex*(en+ree) + SLK
                        float s0 = fmaf(sx * qa.w, (float)acc[mf][nf][2 * hh],     -qa.x);
                        float s1 = fmaf(sx * qb.w, (float)acc[mf][nf][2 * hh + 1], -qb.x);
                        float m0e = fmaf(x1, qa.z, fmaf(rex, qa.y, SLK));
                        float m1e = fmaf(x1, qb.z, fmaf(rex, qb.y, SLK));
                        lowmax = fmaxf(lowmax, fmaxf(s0 - m0e, s1 - m1e));
                        ub[nf][0] = s0 + m0e;
                        ub[nf][1] = s1 + m1e;
                    }
                    atomicMax(&ML[row], fmap(lowmax));
                    // stale-lower threshold is a valid lower bound ->
                    // candidate set stays a superset of the true argmax
                    const unsigned thr = ML[row];
                    #pragma unroll
                    for (int nf = 0; nf < 4; nf++) {
                        const int col = v0 + wn * 32 + nf * 8 + lq * 2;
                        if (fmap(ub[nf][0]) >= thr) {
                            int p = atomicAdd(&CNT[row], 1);
                            if (p < CAP) CAND[row * CAP + p] = (unsigned short)col;
                        }
                        if (fmap(ub[nf][1]) >= thr) {
                            int p = atomicAdd(&CNT[row], 1);
                            if (p < CAP) CAND[row * CAP + p] = (unsigned short)(col + 1);
                        }
                    }
                }
            }
        }
    }
    __syncthreads();   // all pairs' candidate pushes visible before rescore

    // ---- exact fp32 rescore of candidates (warp per row) ----
    for (int rr = 0; rr < 8; rr++) {
        const int row = rr * 8 + w;
        const int r = m0 + row;
        float xr[8];
        const float* xp = g_hflat + (size_t)r * C_DIM;
        #pragma unroll
        for (int i = 0; i < 8; i++) xr[i] = xp[lane + i * 32];

        const int n = CNT[row];
        const bool full = (n > CAP);
        const int total = full ? VOCAB : n;

        float best = -FLT_MAX;
        int bidx = VOCAB;
        for (int j = 0; j < total; j++) {
            const int v = full ? j : (int)CAND[row * CAP + j];
            const float* ev = emb + (size_t)v * C_DIM;
            float p = 0.f;
            #pragma unroll
            for (int i = 0; i < 8; i++) p = fmaf(xr[i], __ldg(&ev[lane + i * 32]), p);
            #pragma unroll
            for (int o = 16; o > 0; o >>= 1) p += __shfl_xor_sync(0xFFFFFFFFu, p, o);
            const float s = p - __ldg(&g_halfnorm[v]);
            if (s > best || (s == best && v < bidx)) { best = s; bidx = v; }
        }
        if (lane == 0) { g_bestscore[r] = best; g_bestidx[r] = bidx; }
    }
}

// ---------------------------------------------------------------------------
__global__ void gather_kernel(const float* __restrict__ emb, float* __restrict__ out) {
    int bc = blockIdx.x;
    int b = bc >> 8, c = bc & 255;
    int t = threadIdx.x;
    #pragma unroll
    for (int u = 0; u < 4; u++) {
        int sp = t + u * 256;
        int n = b * 1024 + sp;
        int idx = g_bestidx[n];
        out[(size_t)bc * 1024 + sp] = __ldg(&emb[(size_t)idx * C_DIM + c]);
        if (c == 0) out[4194304 + n] = (float)idx;
    }
}

__global__ void loss_kernel(float* __restrict__ out) {
    __shared__ float sm[256];
    int t = threadIdx.x;
    float s1 = 0.f, s2 = 0.f;
    for (int i = t; i < 4096; i += 256)  s1 += g_partial[i];
    for (int i = t; i < N_VEC; i += 256) s2 += g_bestscore[i];
    sm[t] = s1 - 2.f * s2;
    __syncthreads();
    #pragma unroll
    for (int o = 128; o > 0; o >>= 1) {
        if (t < o) sm[t] += sm[t + o];
        __syncthreads();
    }
    if (t == 0) out[4210688] = sm[0] / 4194304.f;
}

// ---------------------------------------------------------------------------
extern "C" void kernel_launch(void* const* d_in, const int* in_sizes, int n_in,
                              void* d_out, int out_size) {
    const float* h   = (const float*)d_in[0];
    const float* emb = (const float*)d_in[1];
    float* out = (float*)d_out;

    static bool attr_set = false;
    if (!attr_set) {
        cudaFuncSetAttribute(pass1_kernel,
                             cudaFuncAttributeMaxDynamicSharedMemorySize, SMEM_P1);
        attr_set = true;
    }

    dim3 tgrid(32, 8, 16), tblk(32, 8);
    prep_h_kernel<<<tgrid, tblk>>>(h);
    prep_emb_kernel<<<VOCAB, 256>>>(emb);
    prep_hq_kernel<<<N_VEC / 8, 256>>>();

    pass1_kernel<<<N_VEC / MTILE, 256, SMEM_P1>>>(emb);

    gather_kernel<<<4096, 256>>>(emb, out);
    loss_kernel<<<1, 256>>>(out);
}

// round 14
// speedup vs baseline: 1.3072x; 1.3072x over previous
#include <cuda_runtime.h>
#include <cuda_fp16.h>
#include <cstdint>
#include <cfloat>

#define N_VEC  16384
#define VOCAB  4096
#define C_DIM  256

// rigorous fp16-quantization margin: |s_hat - s_exact| <= MCOEF*||x||*||e|| + SLK
#define MCOEF  1.06e-3f
#define SLK    0.05f

// ---------------------------------------------------------------------------
__device__ float  g_hflat[N_VEC * C_DIM];     // h transposed (N,C) fp32
__device__ __half g_A16[N_VEC * C_DIM];       // fp16 copy
__device__ __half g_B16[VOCAB * C_DIM];       // fp16 codebook
__device__ float  g_halfnorm[VOCAB];          // 0.5*||e||^2 (rescore/loss)
__device__ alignas(16) float2 g_hne[VOCAB];   // (0.5*||e||^2, ||e||) packed
__device__ float  g_xnorm[N_VEC];             // ||x||
__device__ float  g_bestscore[N_VEC];
__device__ int    g_bestidx[N_VEC];
__device__ float  g_partial[4096];

// ---------------------------------------------------------------------------
__device__ __forceinline__ uint32_t smem_u32(const void* p) {
    uint32_t a;
    asm("{ .reg .u64 t; cvta.to.shared.u64 t, %1; cvt.u32.u64 %0, t; }"
        : "=r"(a) : "l"(p));
    return a;
}
__device__ __forceinline__ unsigned fmap(float f) {
    unsigned u = __float_as_uint(f);
    return u ^ ((unsigned)((int)u >> 31) | 0x80000000u);
}
#define CP_ASYNC16(saddr, gptr) \
    asm volatile("cp.async.cg.shared.global [%0], [%1], 16;" \
                 :: "r"(saddr), "l"(gptr) : "memory")
#define CP_COMMIT() asm volatile("cp.async.commit_group;" ::: "memory")
#define CP_WAIT1()  asm volatile("cp.async.wait_group 1;" ::: "memory")
#define CP_WAIT0()  asm volatile("cp.async.wait_group 0;" ::: "memory")

#define MMA16816(c, a, b) \
    asm volatile( \
        "mma.sync.aligned.m16n8k16.row.col.f32.f16.f16.f32 " \
        "{%0,%1,%2,%3}, {%4,%5,%6,%7}, {%8,%9}, {%0,%1,%2,%3};" \
        : "+f"((c)[0]), "+f"((c)[1]), "+f"((c)[2]), "+f"((c)[3]) \
        : "r"((a)[0]), "r"((a)[1]), "r"((a)[2]), "r"((a)[3]), \
          "r"((b)[0]), "r"((b)[1]))

#define LDSM_X4(r0, r1, r2, r3, addr) \
    asm volatile("ldmatrix.sync.aligned.m8n8.x4.shared.b16 {%0,%1,%2,%3}, [%4];" \
                 : "=r"(r0), "=r"(r1), "=r"(r2), "=r"(r3) : "r"(addr))

// ---------------------------------------------------------------------------
// transpose h (B,C,H,W)->(N,C): fp32 + fp16 copies, fused sum(h^2) partial
__global__ void prep_h_kernel(const float* __restrict__ h) {
    __shared__ float tile[32][33];
    __shared__ float rsm[8];
    int b = blockIdx.z, ct = blockIdx.y, st = blockIdx.x;
    int c0 = ct * 32, s0 = st * 32;
    int tx = threadIdx.x, ty = threadIdx.y;
    int t = ty * 32 + tx;

    const float* src = h + ((size_t)b * C_DIM + c0) * 1024 + s0;
    float sq = 0.f;
    #pragma unroll
    for (int i = 0; i < 32; i += 8) {
        float v = src[(size_t)(ty + i) * 1024 + tx];
        tile[ty + i][tx] = v;
        sq = fmaf(v, v, sq);
    }
    __syncthreads();
    size_t rowbase = (size_t)b * 1024 + s0;
    #pragma unroll
    for (int i = 0; i < 32; i += 8) {
        float x = tile[tx][ty + i];
        size_t idx = (rowbase + ty + i) * C_DIM + c0 + tx;
        g_hflat[idx] = x;
        g_A16[idx]   = __float2half_rn(x);
    }
    #pragma unroll
    for (int o = 16; o > 0; o >>= 1) sq += __shfl_down_sync(0xFFFFFFFFu, sq, o);
    if ((t & 31) == 0) rsm[t >> 5] = sq;
    __syncthreads();
    if (t == 0) {
        float tot = 0.f;
        #pragma unroll
        for (int i = 0; i < 8; i++) tot += rsm[i];
        g_partial[(b * 8 + ct) * 32 + st] = tot;
    }
}

__global__ void prep_emb_kernel(const float* __restrict__ emb) {
    int v = blockIdx.x, t = threadIdx.x;
    float x = emb[v * C_DIM + t];
    g_B16[v * C_DIM + t] = __float2half_rn(x);

    float s = x * x;
    __shared__ float sm[8];
    #pragma unroll
    for (int o = 16; o > 0; o >>= 1) s += __shfl_down_sync(0xFFFFFFFFu, s, o);
    if ((t & 31) == 0) sm[t >> 5] = s;
    __syncthreads();
    if (t == 0) {
        float tot = 0.f;
        #pragma unroll
        for (int i = 0; i < 8; i++) tot += sm[i];
        g_halfnorm[v] = 0.5f * tot;
        g_hne[v] = make_float2(0.5f * tot, sqrtf(tot));
    }
}

__global__ void xnorm_kernel() {
    int w = threadIdx.x >> 5, lane = threadIdx.x & 31;
    int r = blockIdx.x * 8 + w;
    const float* xr = g_hflat + (size_t)r * C_DIM;
    float p = 0.f;
    #pragma unroll
    for (int i = 0; i < 8; i++) { float x = xr[lane + i * 32]; p = fmaf(x, x, p); }
    #pragma unroll
    for (int o = 16; o > 0; o >>= 1) p += __shfl_xor_sync(0xFFFFFFFFu, p, o);
    if (lane == 0) g_xnorm[r] = sqrtf(p);
}

// ---------------------------------------------------------------------------
// Fused fp16 GEMM: warp tile 32x64, v-tile N=256, swizzled B (128B rows),
// 2-stage cp.async, register filter + exact rescore.
// 256 CTAs (M tile 64) x 256 threads (8 warps: wm=w&1, wn=w>>1 in 0..3).
// NC = 16 v-tiles * 4 K-chunks(64 halfs) = 64 iterations.
#define MTILE 64
#define LDA   264                 // A halfs/row: 528B == 16 mod 128 -> LDSM ok
#define BSTG  32768               // B stage: 256 rows x 128B (swizzled)
#define CAP   32
#define NC    64
#define OFF_A    0                        // 64*264*2 = 33792
#define OFF_B    33792                    // 2 stages * 32768 = 65536
#define OFF_HNE  99328                    // 2 slots * 256 float2 = 4096
#define OFF_XN   103424                   // 64 floats (+pad)
#define OFF_ML   103680                   // 64 u32
#define OFF_CNT  103936                   // 64 ints
#define OFF_CAND 104192                   // 64*32 u16 = 4096
#define SMEM_P1  108288

__global__ __launch_bounds__(256, 2) void pass1_kernel(const float* __restrict__ emb) {
    extern __shared__ char smem[];
    const uint32_t sb = smem_u32(smem);
    float*    XN  = reinterpret_cast<float*>(smem + OFF_XN);
    unsigned* ML  = reinterpret_cast<unsigned*>(smem + OFF_ML);
    int*      CNT = reinterpret_cast<int*>(smem + OFF_CNT);
    unsigned short* CAND = reinterpret_cast<unsigned short*>(smem + OFF_CAND);

    const int tid = threadIdx.x;
    const int w = tid >> 5, lane = tid & 31;
    const int wm = w & 1, wn = w >> 1;
    const int m0 = blockIdx.x * MTILE;
    const int lg = lane >> 2;
    const int lq = lane & 3;

    if (tid < 64) {
        XN[tid] = __ldg(&g_xnorm[m0 + tid]);
        ML[tid] = 0u;
        CNT[tid] = 0;
    }

    // A ldmatrix lane address (padded layout, bytes)
    const uint32_t aLane = (uint32_t)(((lane & 15) * LDA + (lane >> 4) * 8) * 2);
    const uint32_t aBase0 = sb + OFF_A + (uint32_t)(wm * 32 * LDA * 2) + aLane;

    // B ldmatrix lane constants (swizzled 128B-row layout)
    const int rowB  = (lane & 7) | ((lane >> 4) << 3);   // row within 16-row group
    const int rswB  = lane & 7;                          // swizzle key
    const int segbt = (lane >> 3) & 1;                   // k half-segment
    const uint32_t bWarpRow = (uint32_t)((wn * 64 + rowB) * 128);

    // A tile loader: 64 rows x 512B
    {
        const int lar = tid >> 5, laq = tid & 31;
        #pragma unroll
        for (int i = 0; i < 8; i++) {
            int r = lar + i * 8;
            CP_ASYNC16(sb + OFF_A + (uint32_t)(r * LDA * 2 + laq * 16),
                       g_A16 + (size_t)(m0 + r) * C_DIM + laq * 8);
        }
        CP_COMMIT();
    }

    // prefetch chunk c = (vt = c>>2, kc = c&3): B rows [vt*256,+256) x 64 halfs,
    // stored swizzled: seg s of row r -> r*128 + ((s ^ (r&7))*16).
    // HNE for vt rides with the kc==0 chunk.
    const int tsw = tid & 7;
    #define PREFETCH(c) do {                                                    \
        const int _vt = (c) >> 2, _kc = (c) & 3;                                \
        const uint32_t _dst = sb + OFF_B + (uint32_t)(((c) & 1) * BSTG)         \
                            + (uint32_t)(tid * 128);                            \
        const __half* _src = g_B16 + (size_t)(_vt * 256 + tid) * C_DIM + _kc * 64; \
        _Pragma("unroll")                                                       \
        for (int _s = 0; _s < 8; _s++)                                          \
            CP_ASYNC16(_dst + (uint32_t)(((_s ^ tsw) << 4)), _src + _s * 8);    \
        if (_kc == 0 && tid < 128) {                                            \
            CP_ASYNC16(sb + OFF_HNE + (uint32_t)((_vt & 1) * 2048 + tid * 16),  \
                       reinterpret_cast<const float*>(g_hne) + _vt * 512 + tid * 4); \
        }                                                                       \
        CP_COMMIT();                                                            \
    } while (0)

    PREFETCH(0);

    float acc[2][8][4];

    for (int i = 0; i < NC; i++) {
        // issue next chunk, then wait for chunk i (A group absorbed at i=0)
        if (i < NC - 1) { PREFETCH(i + 1); CP_WAIT1(); }
        else            { CP_WAIT0(); }
        __syncthreads();   // chunk i visible to all warps

        const int kc = i & 3;
        const int vt = i >> 2;

        if (kc == 0) {
            #pragma unroll
            for (int mf = 0; mf < 2; mf++)
                #pragma unroll
                for (int nf = 0; nf < 8; nf++)
                    #pragma unroll
                    for (int q = 0; q < 4; q++) acc[mf][nf][q] = 0.f;
        }

        const uint32_t bStage = sb + OFF_B + (uint32_t)((i & 1) * BSTG) + bWarpRow;
        const uint32_t aK = (uint32_t)(kc * 64 * 2);

        #pragma unroll
        for (int ks = 0; ks < 4; ks++) {
            uint32_t a[2][4], b[8][2];
            const uint32_t ka = aK + (uint32_t)(ks * 32);
            const uint32_t sega = (uint32_t)((((ks * 2 + segbt) ^ rswB)) << 4);
            LDSM_X4(a[0][0], a[0][1], a[0][2], a[0][3], aBase0 + ka);
            LDSM_X4(a[1][0], a[1][1], a[1][2], a[1][3],
                    aBase0 + (uint32_t)(16 * LDA * 2) + ka);
            #pragma unroll
            for (int g = 0; g < 4; g++)
                LDSM_X4(b[2 * g][0], b[2 * g][1], b[2 * g + 1][0], b[2 * g + 1][1],
                        bStage + (uint32_t)(g * 16 * 128) + sega);
            #pragma unroll
            for (int mf = 0; mf < 2; mf++)
                #pragma unroll
                for (int nf = 0; nf < 8; nf++)
                    MMA16816(acc[mf][nf], a[mf], b[nf]);
        }

        if (kc == 3) {
            // ---- register epilogue for v-tile [vt*256, +256) ----
            const float* HNE = reinterpret_cast<const float*>(
                smem + OFF_HNE + (vt & 1) * 2048);
            const int v0 = vt << 8;
            const int rbase = wm * 32 + lg;
            #pragma unroll
            for (int mf = 0; mf < 2; mf++) {
                #pragma unroll
                for (int hh = 0; hh < 2; hh++) {
                    const int row = rbase + mf * 16 + hh * 8;
                    const float mx = MCOEF * XN[row];
                    float lowmax = -FLT_MAX;
                    float ub[8][2];
                    #pragma unroll
                    for (int nf = 0; nf < 8; nf++) {
                        const int col = wn * 64 + nf * 8 + lq * 2;
                        float4 q4 = *reinterpret_cast<const float4*>(HNE + col * 2);
                        float s0 = acc[mf][nf][2 * hh]     - q4.x;
                        float s1 = acc[mf][nf][2 * hh + 1] - q4.z;
                        float me0 = fmaf(mx, q4.y, SLK);
                        float me1 = fmaf(mx, q4.w, SLK);
                        lowmax = fmaxf(lowmax, fmaxf(s0 - me0, s1 - me1));
                        ub[nf][0] = s0 + me0;
                        ub[nf][1] = s1 + me1;
                    }
                    atomicMax(&ML[row], fmap(lowmax));
                    // stale-lower threshold is still a valid lower bound ->
                    // candidate set stays a superset of the true argmax
                    const unsigned thr = ML[row];
                    #pragma unroll
                    for (int nf = 0; nf < 8; nf++) {
                        const int col = v0 + wn * 64 + nf * 8 + lq * 2;
                        if (fmap(ub[nf][0]) >= thr) {
                            int p = atomicAdd(&CNT[row], 1);
                            if (p < CAP) CAND[row * CAP + p] = (unsigned short)col;
                        }
                        if (fmap(ub[nf][1]) >= thr) {
                            int p = atomicAdd(&CNT[row], 1);
                            if (p < CAP) CAND[row * CAP + p] = (unsigned short)(col + 1);
                        }
                    }
                }
            }
        }
        __syncthreads();   // reads of stage i&1 done before next prefetch writes
    }
    __syncthreads();

    // ---- exact fp32 rescore of candidates (warp per row) ----
    for (int rr = 0; rr < 8; rr++) {
        const int row = rr * 8 + w;
        const int r = m0 + row;
        float xr[8];
        const float* xp = g_hflat + (size_t)r * C_DIM;
        #pragma unroll
        for (int i = 0; i < 8; i++) xr[i] = xp[lane + i * 32];

        const int n = CNT[row];
        const bool full = (n > CAP);
        const int total = full ? VOCAB : n;

        float best = -FLT_MAX;
        int bidx = VOCAB;
        for (int j = 0; j < total; j++) {
            const int v = full ? j : (int)CAND[row * CAP + j];
            const float* ev = emb + (size_t)v * C_DIM;
            float p = 0.f;
            #pragma unroll
            for (int i = 0; i < 8; i++) p = fmaf(xr[i], __ldg(&ev[lane + i * 32]), p);
            #pragma unroll
            for (int o = 16; o > 0; o >>= 1) p += __shfl_xor_sync(0xFFFFFFFFu, p, o);
            const float s = p - __ldg(&g_halfnorm[v]);
            if (s > best || (s == best && v < bidx)) { best = s; bidx = v; }
        }
        if (lane == 0) { g_bestscore[r] = best; g_bestidx[r] = bidx; }
    }
}

// ---------------------------------------------------------------------------
__global__ void gather_kernel(const float* __restrict__ emb, float* __restrict__ out) {
    int bc = blockIdx.x;
    int b = bc >> 8, c = bc & 255;
    int t = threadIdx.x;
    #pragma unroll
    for (int u = 0; u < 4; u++) {
        int sp = t + u * 256;
        int n = b * 1024 + sp;
        int idx = g_bestidx[n];
        out[(size_t)bc * 1024 + sp] = __ldg(&emb[(size_t)idx * C_DIM + c]);
        if (c == 0) out[4194304 + n] = (float)idx;
    }
}

__global__ void loss_kernel(float* __restrict__ out) {
    __shared__ float sm[256];
    int t = threadIdx.x;
    float s1 = 0.f, s2 = 0.f;
    for (int i = t; i < 4096; i += 256)  s1 += g_partial[i];
    for (int i = t; i < N_VEC; i += 256) s2 += g_bestscore[i];
    sm[t] = s1 - 2.f * s2;
    __syncthreads();
    #pragma unroll
    for (int o = 128; o > 0; o >>= 1) {
        if (t < o) sm[t] += sm[t + o];
        __syncthreads();
    }
    if (t == 0) out[4210688] = sm[0] / 4194304.f;
}

// ---------------------------------------------------------------------------
extern "C" void kernel_launch(void* const* d_in, const int* in_sizes, int n_in,
                              void* d_out, int out_size) {
    const float* h   = (const float*)d_in[0];
    const float* emb = (const float*)d_in[1];
    float* out = (float*)d_out;

    static bool attr_set = false;
    if (!attr_set) {
        cudaFuncSetAttribute(pass1_kernel,
                             cudaFuncAttributeMaxDynamicSharedMemorySize, SMEM_P1);
        attr_set = true;
    }

    dim3 tgrid(32, 8, 16), tblk(32, 8);
    prep_h_kernel<<<tgrid, tblk>>>(h);
    prep_emb_kernel<<<VOCAB, 256>>>(emb);
    xnorm_kernel<<<N_VEC / 8, 256>>>();

    pass1_kernel<<<N_VEC / MTILE, 256, SMEM_P1>>>(emb);

    gather_kernel<<<4096, 256>>>(emb, out);
    loss_kernel<<<1, 256>>>(out);
}

// round 15
// speedup vs baseline: 1.5903x; 1.2165x over previous
#include <cuda_runtime.h>
#include <cuda_fp16.h>
#include <cstdint>
#include <cfloat>

#define N_VEC  16384
#define VOCAB  4096
#define C_DIM  256

// rigorous fp16-quantization margin: |s_hat - s_exact| <= MCOEF*||x||*||e|| + SLK
#define MCOEF  1.06e-3f
#define SLK    0.05f

// ---------------------------------------------------------------------------
__device__ float  g_hflat[N_VEC * C_DIM];     // h transposed (N,C) fp32
__device__ __half g_A16[N_VEC * C_DIM];       // fp16 copy
__device__ __half g_B16[VOCAB * C_DIM];       // fp16 codebook
__device__ float  g_halfnorm[VOCAB];          // 0.5*||e||^2 (rescore/loss)
__device__ alignas(16) float2 g_hne[VOCAB];   // (0.5*||e||^2, ||e||) packed
__device__ float  g_xnorm[N_VEC];             // ||x||
__device__ float  g_bestscore[N_VEC];
__device__ int    g_bestidx[N_VEC];
__device__ float  g_partial[4096];

// ---------------------------------------------------------------------------
__device__ __forceinline__ uint32_t smem_u32(const void* p) {
    uint32_t a;
    asm("{ .reg .u64 t; cvta.to.shared.u64 t, %1; cvt.u32.u64 %0, t; }"
        : "=r"(a) : "l"(p));
    return a;
}
__device__ __forceinline__ unsigned fmap(float f) {
    unsigned u = __float_as_uint(f);
    return u ^ ((unsigned)((int)u >> 31) | 0x80000000u);
}
#define CP_ASYNC16(saddr, gptr) \
    asm volatile("cp.async.cg.shared.global [%0], [%1], 16;" \
                 :: "r"(saddr), "l"(gptr) : "memory")
#define CP_COMMIT() asm volatile("cp.async.commit_group;" ::: "memory")
#define CP_WAIT1()  asm volatile("cp.async.wait_group 1;" ::: "memory")
#define CP_WAIT0()  asm volatile("cp.async.wait_group 0;" ::: "memory")

#define MMA16816(c, a, b) \
    asm volatile( \
        "mma.sync.aligned.m16n8k16.row.col.f32.f16.f16.f32 " \
        "{%0,%1,%2,%3}, {%4,%5,%6,%7}, {%8,%9}, {%0,%1,%2,%3};" \
        : "+f"((c)[0]), "+f"((c)[1]), "+f"((c)[2]), "+f"((c)[3]) \
        : "r"((a)[0]), "r"((a)[1]), "r"((a)[2]), "r"((a)[3]), \
          "r"((b)[0]), "r"((b)[1]))

#define LDSM_X4(r0, r1, r2, r3, addr) \
    asm volatile("ldmatrix.sync.aligned.m8n8.x4.shared.b16 {%0,%1,%2,%3}, [%4];" \
                 : "=r"(r0), "=r"(r1), "=r"(r2), "=r"(r3) : "r"(addr))

// ---------------------------------------------------------------------------
// transpose h (B,C,H,W)->(N,C): fp32 + fp16 copies, fused sum(h^2) partial
__global__ void prep_h_kernel(const float* __restrict__ h) {
    __shared__ float tile[32][33];
    __shared__ float rsm[8];
    int b = blockIdx.z, ct = blockIdx.y, st = blockIdx.x;
    int c0 = ct * 32, s0 = st * 32;
    int tx = threadIdx.x, ty = threadIdx.y;
    int t = ty * 32 + tx;

    const float* src = h + ((size_t)b * C_DIM + c0) * 1024 + s0;
    float sq = 0.f;
    #pragma unroll
    for (int i = 0; i < 32; i += 8) {
        float v = src[(size_t)(ty + i) * 1024 + tx];
        tile[ty + i][tx] = v;
        sq = fmaf(v, v, sq);
    }
    __syncthreads();
    size_t rowbase = (size_t)b * 1024 + s0;
    #pragma unroll
    for (int i = 0; i < 32; i += 8) {
        float x = tile[tx][ty + i];
        size_t idx = (rowbase + ty + i) * C_DIM + c0 + tx;
        g_hflat[idx] = x;
        g_A16[idx]   = __float2half_rn(x);
    }
    #pragma unroll
    for (int o = 16; o > 0; o >>= 1) sq += __shfl_down_sync(0xFFFFFFFFu, sq, o);
    if ((t & 31) == 0) rsm[t >> 5] = sq;
    __syncthreads();
    if (t == 0) {
        float tot = 0.f;
        #pragma unroll
        for (int i = 0; i < 8; i++) tot += rsm[i];
        g_partial[(b * 8 + ct) * 32 + st] = tot;
    }
}

__global__ void prep_emb_kernel(const float* __restrict__ emb) {
    int v = blockIdx.x, t = threadIdx.x;
    float x = emb[v * C_DIM + t];
    g_B16[v * C_DIM + t] = __float2half_rn(x);

    float s = x * x;
    __shared__ float sm[8];
    #pragma unroll
    for (int o = 16; o > 0; o >>= 1) s += __shfl_down_sync(0xFFFFFFFFu, s, o);
    if ((t & 31) == 0) sm[t >> 5] = s;
    __syncthreads();
    if (t == 0) {
        float tot = 0.f;
        #pragma unroll
        for (int i = 0; i < 8; i++) tot += sm[i];
        g_halfnorm[v] = 0.5f * tot;
        g_hne[v] = make_float2(0.5f * tot, sqrtf(tot));
    }
}

__global__ void xnorm_kernel() {
    int w = threadIdx.x >> 5, lane = threadIdx.x & 31;
    int r = blockIdx.x * 8 + w;
    const float* xr = g_hflat + (size_t)r * C_DIM;
    float p = 0.f;
    #pragma unroll
    for (int i = 0; i < 8; i++) { float x = xr[lane + i * 32]; p = fmaf(x, x, p); }
    #pragma unroll
    for (int o = 16; o > 0; o >>= 1) p += __shfl_xor_sync(0xFFFFFFFFu, p, o);
    if (lane == 0) g_xnorm[r] = sqrtf(p);
}

// ---------------------------------------------------------------------------
// Fused fp16 GEMM + filter + rescore at 3 CTAs/SM (24 warps).
// Compact swizzled smem: A 64x512B (32.8KB), 2 B stages 128x128B (16KB each).
// 256 CTAs (M tile 64) x 256 threads (wm=w&1, wn=w>>1). Warp tile 32x32.
// v-tile N=128 (32 tiles); K chunks of 64 halfs (4 per v-tile). NC=128.
#define MTILE 64
#define CAP   32
#define NC    128
#define OFF_A    0                        // 64 * 512 = 32768
#define OFF_B    32768                    // 2 stages * 16384 = 32768
#define OFF_HNE  65536                    // 2 slots * 128 float2 = 2048
#define OFF_XN   67584                    // 64 floats
#define OFF_ML   67840                    // 64 u32
#define OFF_CNT  68096                    // 64 ints
#define OFF_CAND 68352                    // 64*32 u16 = 4096
#define SMEM_P1  72448                    // x3 = 217,344 <= SM carveout

__global__ __launch_bounds__(256, 3) void pass1_kernel(const float* __restrict__ emb) {
    extern __shared__ char smem[];
    const uint32_t sb = smem_u32(smem);
    float*    XN  = reinterpret_cast<float*>(smem + OFF_XN);
    unsigned* ML  = reinterpret_cast<unsigned*>(smem + OFF_ML);
    int*      CNT = reinterpret_cast<int*>(smem + OFF_CNT);
    unsigned short* CAND = reinterpret_cast<unsigned short*>(smem + OFF_CAND);

    const int tid = threadIdx.x;
    const int w = tid >> 5, lane = tid & 31;
    const int wm = w & 1, wn = w >> 1;
    const int m0 = blockIdx.x * MTILE;
    const int lg = lane >> 2;
    const int lq = lane & 3;

    if (tid < 64) {
        XN[tid] = __ldg(&g_xnorm[m0 + tid]);
        ML[tid] = 0u;
        CNT[tid] = 0;
    }

    // ldmatrix lane constants (swizzled layouts)
    const int key = lane & 7;          // swizzle key (row mod 8)
    const int e   = lane >> 4;         // k half-segment selector for A
    // A: row = wm*32 + mf*16 + (lane&15); 512B rows
    const uint32_t aBase = sb + OFF_A + (uint32_t)((wm * 32 + (lane & 15)) * 512);
    // B: rowB = (lane&7)|((lane>>4)<<3) within 16-row group; 128B rows
    const int rowB  = (lane & 7) | ((lane >> 4) << 3);
    const int segbt = (lane >> 3) & 1;
    const uint32_t bWarpRow = (uint32_t)((wn * 32 + rowB) * 128);

    // ---- A tile load: 64 rows x 512B, swizzled (seg s of row r at
    //      r*512 + (s>>3)*128 + ((s&7 ^ r&7)<<4)), 8 segs per thread ----
    {
        const int ar = tid >> 2;               // 0..63
        const int ablk = tid & 3;              // 128B block (= s>>3)
        const int akey = ar & 7;
        const uint32_t adst = sb + OFF_A + (uint32_t)(ar * 512 + ablk * 128);
        const __half* asrc = g_A16 + (size_t)(m0 + ar) * C_DIM + ablk * 64;
        #pragma unroll
        for (int j = 0; j < 8; j++)
            CP_ASYNC16(adst + (uint32_t)((j ^ akey) << 4), asrc + j * 8);
        CP_COMMIT();
    }

    // prefetch chunk c = (vt = c>>2, kc = c&3): B rows [vt*128,+128) x 64 halfs;
    // row r stored at stage + r*128, seg s at ((s ^ r&7)<<4). HNE rides kc==0.
    const int lbr = tid >> 1;                  // 0..127
    const int lbs = (tid & 1) * 4;             // first of 4 segs
    const int lbk = lbr & 7;
    #define PREFETCH(c) do {                                                    \
        const int _vt = (c) >> 2, _kc = (c) & 3;                                \
        const uint32_t _dst = sb + OFF_B + (uint32_t)(((c) & 1) * 16384)        \
                            + (uint32_t)(lbr * 128);                            \
        const __half* _src = g_B16 + (size_t)(_vt * 128 + lbr) * C_DIM          \
                           + _kc * 64 + lbs * 8;                                \
        _Pragma("unroll")                                                       \
        for (int _j = 0; _j < 4; _j++)                                          \
            CP_ASYNC16(_dst + (uint32_t)((((lbs + _j) ^ lbk)) << 4), _src + _j * 8); \
        if (_kc == 0 && tid < 64) {                                             \
            CP_ASYNC16(sb + OFF_HNE + (uint32_t)((_vt & 1) * 1024 + tid * 16),  \
                       reinterpret_cast<const float*>(g_hne) + _vt * 256 + tid * 4); \
        }                                                                       \
        CP_COMMIT();                                                            \
    } while (0)

    PREFETCH(0);

    float acc[2][4][4];

    for (int i = 0; i < NC; i++) {
        if (i < NC - 1) { PREFETCH(i + 1); CP_WAIT1(); }
        else            { CP_WAIT0(); }
        __syncthreads();   // chunk i visible to all warps

        const int kc = i & 3;
        const int vt = i >> 2;

        if (kc == 0) {
            #pragma unroll
            for (int mf = 0; mf < 2; mf++)
                #pragma unroll
                for (int nf = 0; nf < 4; nf++)
                    #pragma unroll
                    for (int q = 0; q < 4; q++) acc[mf][nf][q] = 0.f;
        }

        const uint32_t aKc = aBase + (uint32_t)(kc * 128);
        const uint32_t bStage = sb + OFF_B + (uint32_t)((i & 1) * 16384) + bWarpRow;

        #pragma unroll
        for (int ks = 0; ks < 4; ks++) {
            uint32_t a[2][4], b[4][2];
            const uint32_t asw = (uint32_t)((((ks * 2 + e) ^ key)) << 4);
            const uint32_t bsw = (uint32_t)((((ks * 2 + segbt) ^ key)) << 4);
            LDSM_X4(a[0][0], a[0][1], a[0][2], a[0][3], aKc + asw);
            LDSM_X4(a[1][0], a[1][1], a[1][2], a[1][3], aKc + 8192u + asw);
            LDSM_X4(b[0][0], b[0][1], b[1][0], b[1][1], bStage + bsw);
            LDSM_X4(b[2][0], b[2][1], b[3][0], b[3][1],
                    bStage + (uint32_t)(16 * 128) + bsw);
            #pragma unroll
            for (int mf = 0; mf < 2; mf++)
                #pragma unroll
                for (int nf = 0; nf < 4; nf++)
                    MMA16816(acc[mf][nf], a[mf], b[nf]);
        }

        if (kc == 3) {
            // ---- register epilogue for v-tile [vt*128, +128) ----
            const float* HNE = reinterpret_cast<const float*>(
                smem + OFF_HNE + (vt & 1) * 1024);
            const int v0 = vt << 7;
            const int rbase = wm * 32 + lg;
            #pragma unroll
            for (int mf = 0; mf < 2; mf++) {
                #pragma unroll
                for (int hh = 0; hh < 2; hh++) {
                    const int row = rbase + mf * 16 + hh * 8;
                    const float mx = MCOEF * XN[row];
                    float lowmax = -FLT_MAX;
                    float ub[4][2];
                    #pragma unroll
                    for (int nf = 0; nf < 4; nf++) {
                        const int col = wn * 32 + nf * 8 + lq * 2;
                        float4 q4 = *reinterpret_cast<const float4*>(HNE + col * 2);
                        float s0 = acc[mf][nf][2 * hh]     - q4.x;
                        float s1 = acc[mf][nf][2 * hh + 1] - q4.z;
                        float me0 = fmaf(mx, q4.y, SLK);
                        float me1 = fmaf(mx, q4.w, SLK);
                        lowmax = fmaxf(lowmax, fmaxf(s0 - me0, s1 - me1));
                        ub[nf][0] = s0 + me0;
                        ub[nf][1] = s1 + me1;
                    }
                    atomicMax(&ML[row], fmap(lowmax));
                    // stale-lower threshold is still a valid lower bound ->
                    // candidate set stays a superset of the true argmax
                    const unsigned thr = ML[row];
                    #pragma unroll
                    for (int nf = 0; nf < 4; nf++) {
                        const int col = v0 + wn * 32 + nf * 8 + lq * 2;
                        if (fmap(ub[nf][0]) >= thr) {
                            int p = atomicAdd(&CNT[row], 1);
                            if (p < CAP) CAND[row * CAP + p] = (unsigned short)col;
                        }
                        if (fmap(ub[nf][1]) >= thr) {
                            int p = atomicAdd(&CNT[row], 1);
                            if (p < CAP) CAND[row * CAP + p] = (unsigned short)(col + 1);
                        }
                    }
                }
            }
        }
        __syncthreads();   // stage i&1 reads done before next prefetch writes
    }
    __syncthreads();

    // ---- exact fp32 rescore of candidates (warp per row) ----
    for (int rr = 0; rr < 8; rr++) {
        const int row = rr * 8 + w;
        const int r = m0 + row;
        float xr[8];
        const float* xp = g_hflat + (size_t)r * C_DIM;
        #pragma unroll
        for (int i = 0; i < 8; i++) xr[i] = xp[lane + i * 32];

        const int n = CNT[row];
        const bool full = (n > CAP);
        const int total = full ? VOCAB : n;

        float best = -FLT_MAX;
        int bidx = VOCAB;
        for (int j = 0; j < total; j++) {
            const int v = full ? j : (int)CAND[row * CAP + j];
            const float* ev = emb + (size_t)v * C_DIM;
            float p = 0.f;
            #pragma unroll
            for (int i = 0; i < 8; i++) p = fmaf(xr[i], __ldg(&ev[lane + i * 32]), p);
            #pragma unroll
            for (int o = 16; o > 0; o >>= 1) p += __shfl_xor_sync(0xFFFFFFFFu, p, o);
            const float s = p - __ldg(&g_halfnorm[v]);
            if (s > best || (s == best && v < bidx)) { best = s; bidx = v; }
        }
        if (lane == 0) { g_bestscore[r] = best; g_bestidx[r] = bidx; }
    }
}

// ---------------------------------------------------------------------------
__global__ void gather_kernel(const float* __restrict__ emb, float* __restrict__ out) {
    int bc = blockIdx.x;
    int b = bc >> 8, c = bc & 255;
    int t = threadIdx.x;
    #pragma unroll
    for (int u = 0; u < 4; u++) {
        int sp = t + u * 256;
        int n = b * 1024 + sp;
        int idx = g_bestidx[n];
        out[(size_t)bc * 1024 + sp] = __ldg(&emb[(size_t)idx * C_DIM + c]);
        if (c == 0) out[4194304 + n] = (float)idx;
    }
}

__global__ void loss_kernel(float* __restrict__ out) {
    __shared__ float sm[256];
    int t = threadIdx.x;
    float s1 = 0.f, s2 = 0.f;
    for (int i = t; i < 4096; i += 256)  s1 += g_partial[i];
    for (int i = t; i < N_VEC; i += 256) s2 += g_bestscore[i];
    sm[t] = s1 - 2.f * s2;
    __syncthreads();
    #pragma unroll
    for (int o = 128; o > 0; o >>= 1) {
        if (t < o) sm[t] += sm[t + o];
        __syncthreads();
    }
    if (t == 0) out[4210688] = sm[0] / 4194304.f;
}

// ---------------------------------------------------------------------------
extern "C" void kernel_launch(void* const* d_in, const int* in_sizes, int n_in,
                              void* d_out, int out_size) {
    const float* h   = (const float*)d_in[0];
    const float* emb = (const float*)d_in[1];
    float* out = (float*)d_out;

    static bool attr_set = false;
    if (!attr_set) {
        cudaFuncSetAttribute(pass1_kernel,
                             cudaFuncAttributeMaxDynamicSharedMemorySize, SMEM_P1);
        attr_set = true;
    }

    dim3 tgrid(32, 8, 16), tblk(32, 8);
    prep_h_kernel<<<tgrid, tblk>>>(h);
    prep_emb_kernel<<<VOCAB, 256>>>(emb);
    xnorm_kernel<<<N_VEC / 8, 256>>>();

    pass1_kernel<<<N_VEC / MTILE, 256, SMEM_P1>>>(emb);

    gather_kernel<<<4096, 256>>>(emb, out);
    loss_kernel<<<1, 256>>>(out);
}

// round 16
// speedup vs baseline: 1.8342x; 1.1534x over previous
#include <cuda_runtime.h>
#include <cuda_fp16.h>
#include <cstdint>
#include <cfloat>

#define N_VEC  16384
#define VOCAB  4096
#define C_DIM  256

// rigorous fp16-quantization margin: |s_hat - s_exact| <= MCOEF*||x||*||e|| + SLK
#define MCOEF  1.06e-3f
#define SLK    0.05f

// ---------------------------------------------------------------------------
__device__ float  g_hflat[N_VEC * C_DIM];     // h transposed (N,C) fp32
__device__ __half g_A16[N_VEC * C_DIM];       // fp16 copy
__device__ __half g_B16[VOCAB * C_DIM];       // fp16 codebook
__device__ float  g_halfnorm[VOCAB];          // 0.5*||e||^2
__device__ float  g_enorm[VOCAB];             // ||e||
__device__ float  g_xnorm[N_VEC];             // ||x||
__device__ float  g_bestscore[N_VEC];
__device__ float  g_partial[4096];

// ---------------------------------------------------------------------------
__device__ __forceinline__ uint32_t smem_u32(const void* p) {
    uint32_t a;
    asm("{ .reg .u64 t; cvta.to.shared.u64 t, %1; cvt.u32.u64 %0, t; }"
        : "=r"(a) : "l"(p));
    return a;
}
__device__ __forceinline__ unsigned fmap(float f) {
    unsigned u = __float_as_uint(f);
    return u ^ ((unsigned)((int)u >> 31) | 0x80000000u);
}
#define CP_ASYNC16(saddr, gptr) \
    asm volatile("cp.async.cg.shared.global [%0], [%1], 16;" \
                 :: "r"(saddr), "l"(gptr) : "memory")
#define CP_COMMIT() asm volatile("cp.async.commit_group;" ::: "memory")
#define CP_WAIT1()  asm volatile("cp.async.wait_group 1;" ::: "memory")
#define CP_WAIT0()  asm volatile("cp.async.wait_group 0;" ::: "memory")

#define MMA16816(c, a, b) \
    asm volatile( \
        "mma.sync.aligned.m16n8k16.row.col.f32.f16.f16.f32 " \
        "{%0,%1,%2,%3}, {%4,%5,%6,%7}, {%8,%9}, {%0,%1,%2,%3};" \
        : "+f"((c)[0]), "+f"((c)[1]), "+f"((c)[2]), "+f"((c)[3]) \
        : "r"((a)[0]), "r"((a)[1]), "r"((a)[2]), "r"((a)[3]), \
          "r"((b)[0]), "r"((b)[1]))

#define LDSM_X4(r0, r1, r2, r3, addr) \
    asm volatile("ldmatrix.sync.aligned.m8n8.x4.shared.b16 {%0,%1,%2,%3}, [%4];" \
                 : "=r"(r0), "=r"(r1), "=r"(r2), "=r"(r3) : "r"(addr))

// ---------------------------------------------------------------------------
// transpose h (B,C,H,W)->(N,C): fp32 + fp16 copies, fused sum(h^2) partial
__global__ void prep_h_kernel(const float* __restrict__ h) {
    __shared__ float tile[32][33];
    __shared__ float rsm[8];
    int b = blockIdx.z, ct = blockIdx.y, st = blockIdx.x;
    int c0 = ct * 32, s0 = st * 32;
    int tx = threadIdx.x, ty = threadIdx.y;
    int t = ty * 32 + tx;

    const float* src = h + ((size_t)b * C_DIM + c0) * 1024 + s0;
    float sq = 0.f;
    #pragma unroll
    for (int i = 0; i < 32; i += 8) {
        float v = src[(size_t)(ty + i) * 1024 + tx];
        tile[ty + i][tx] = v;
        sq = fmaf(v, v, sq);
    }
    __syncthreads();
    size_t rowbase = (size_t)b * 1024 + s0;
    #pragma unroll
    for (int i = 0; i < 32; i += 8) {
        float x = tile[tx][ty + i];
        size_t idx = (rowbase + ty + i) * C_DIM + c0 + tx;
        g_hflat[idx] = x;
        g_A16[idx]   = __float2half_rn(x);
    }
    #pragma unroll
    for (int o = 16; o > 0; o >>= 1) sq += __shfl_down_sync(0xFFFFFFFFu, sq, o);
    if ((t & 31) == 0) rsm[t >> 5] = sq;
    __syncthreads();
    if (t == 0) {
        float tot = 0.f;
        #pragma unroll
        for (int i = 0; i < 8; i++) tot += rsm[i];
        g_partial[(b * 8 + ct) * 32 + st] = tot;
    }
}

__global__ void prep_emb_kernel(const float* __restrict__ emb) {
    int v = blockIdx.x, t = threadIdx.x;
    float x = emb[v * C_DIM + t];
    g_B16[v * C_DIM + t] = __float2half_rn(x);

    float s = x * x;
    __shared__ float sm[8];
    #pragma unroll
    for (int o = 16; o > 0; o >>= 1) s += __shfl_down_sync(0xFFFFFFFFu, s, o);
    if ((t & 31) == 0) sm[t >> 5] = s;
    __syncthreads();
    if (t == 0) {
        float tot = 0.f;
        #pragma unroll
        for (int i = 0; i < 8; i++) tot += sm[i];
        g_halfnorm[v] = 0.5f * tot;
        g_enorm[v]    = sqrtf(tot);
    }
}

__global__ void xnorm_kernel() {
    int w = threadIdx.x >> 5, lane = threadIdx.x & 31;
    int r = blockIdx.x * 8 + w;
    const float* xr = g_hflat + (size_t)r * C_DIM;
    float p = 0.f;
    #pragma unroll
    for (int i = 0; i < 8; i++) { float x = xr[lane + i * 32]; p = fmaf(x, x, p); }
    #pragma unroll
    for (int o = 16; o > 0; o >>= 1) p += __shfl_xor_sync(0xFFFFFFFFu, p, o);
    if (lane == 0) g_xnorm[r] = sqrtf(p);
}

// ---------------------------------------------------------------------------
// Fused mma.sync GEMM (ldmatrix fragments, R8 mainloop) + register filter +
// exact rescore + fused z_q gather and indices output.
// 256 CTAs (M tile 64) x 256 threads (8 warps: wm in {0,1} x wn in {0..3}).
// Warp tile 32x32. v-tile N=128, K chunks of 128 (2 per v-tile).
#define MTILE 64
#define LDA   264        // halfs: row stride 528B == 16 mod 128 -> LDSM conflict-free
#define LDB   136        // halfs: row stride 272B == 16 mod 128 -> LDSM conflict-free
#define CAP   32
#define OFF_A    0                        // 64*264*2   = 33792
#define OFF_B    33792                    // 2*128*136*2= 69632
#define OFF_XN   103424                   // 64 floats
#define OFF_ML   103680                   // 64 u32 (reused as IDX after rescore)
#define OFF_CNT  103936                   // 64 ints
#define OFF_CAND 104192                   // 64*32 u16  = 4096
#define SMEM_P1  108288

__global__ __launch_bounds__(256, 2) void pass1_kernel(const float* __restrict__ emb,
                                                       float* __restrict__ out) {
    extern __shared__ char smem[];
    const uint32_t sb = smem_u32(smem);
    float*    XN  = reinterpret_cast<float*>(smem + OFF_XN);
    unsigned* ML  = reinterpret_cast<unsigned*>(smem + OFF_ML);
    int*      CNT = reinterpret_cast<int*>(smem + OFF_CNT);
    unsigned short* CAND = reinterpret_cast<unsigned short*>(smem + OFF_CAND);

    const int tid = threadIdx.x;
    const int w = tid >> 5, lane = tid & 31;
    const int wm = w & 1, wn = w >> 1;
    const int m0 = blockIdx.x * MTILE;
    const int lg = lane >> 2;        // group id 0..7
    const int lq = lane & 3;         // quad id 0..3

    if (tid < 64) {
        XN[tid] = __ldg(&g_xnorm[m0 + tid]);
        ML[tid] = 0u;                 // maps to "below -inf"
        CNT[tid] = 0;
    }

    // ldmatrix lane-address offsets (bytes)
    const uint32_t aLane = (uint32_t)(((lane & 15) * LDA + (lane >> 4) * 8) * 2);
    const uint32_t aBase0 = sb + OFF_A + (uint32_t)(wm * 32 * LDA * 2) + aLane;
    const uint32_t bLane = (uint32_t)(
        ((((lane & 7) | ((lane >> 4) << 3)) * LDB) + ((lane >> 3) & 1) * 8) * 2);

    // loader constants
    const int ldr = tid >> 4, ldq = tid & 15;          // B tile: 16 rows/iter
    const int lar = tid >> 5, laq = tid & 31;          // A tile: 8 rows/iter

    // resident A tile: 64 rows x 512B
    #pragma unroll
    for (int i = 0; i < 8; i++) {
        int r = lar + i * 8;
        CP_ASYNC16(sb + OFF_A + (uint32_t)(r * LDA * 2 + laq * 16),
                   g_A16 + (size_t)(m0 + r) * C_DIM + laq * 8);
    }
    CP_COMMIT();
    // B chunk 0 into stage 0 (128 rows x 256B)
    #pragma unroll
    for (int i = 0; i < 8; i++) {
        int r = ldr + i * 16;
        CP_ASYNC16(sb + OFF_B + (uint32_t)(r * LDB * 2 + ldq * 16),
                   g_B16 + (size_t)r * C_DIM + ldq * 8);
    }
    CP_COMMIT();

    float acc[2][4][4];

    for (int gc = 0; gc < 64; gc++) {
        const int kc = gc & 1;
        const int v0 = (gc >> 1) << 7;

        // prefetch next chunk into the other stage (end-of-loop barrier
        // separates the reads of the stage being overwritten)
        if (gc < 63) {
            const int ng = gc + 1;
            const int nv0 = (ng >> 1) << 7;
            const int nk0 = (ng & 1) * 128;
            const uint32_t dstb = sb + OFF_B + (uint32_t)((ng & 1) * (128 * LDB * 2));
            #pragma unroll
            for (int i = 0; i < 8; i++) {
                int r = ldr + i * 16;
                CP_ASYNC16(dstb + (uint32_t)(r * LDB * 2 + ldq * 16),
                           g_B16 + (size_t)(nv0 + r) * C_DIM + nk0 + ldq * 8);
            }
            CP_COMMIT();
            CP_WAIT1();
        } else {
            CP_WAIT0();
        }
        __syncthreads();

        if (kc == 0) {
            #pragma unroll
            for (int mf = 0; mf < 2; mf++)
                #pragma unroll
                for (int nf = 0; nf < 4; nf++)
                    #pragma unroll
                    for (int i = 0; i < 4; i++) acc[mf][nf][i] = 0.f;
        }

        const uint32_t bStage = sb + OFF_B + (uint32_t)((gc & 1) * (128 * LDB * 2))
                              + (uint32_t)(wn * 32 * LDB * 2) + bLane;
        const uint32_t aK = (uint32_t)(kc * 128 * 2);

        #pragma unroll
        for (int ks = 0; ks < 8; ks++) {
            uint32_t a[2][4], b[4][2];
            const uint32_t ka = aK + (uint32_t)(ks * 32);    // ks*16 halfs
            const uint32_t kb = (uint32_t)(ks * 32);
            LDSM_X4(a[0][0], a[0][1], a[0][2], a[0][3], aBase0 + ka);
            LDSM_X4(a[1][0], a[1][1], a[1][2], a[1][3],
                    aBase0 + (uint32_t)(16 * LDA * 2) + ka);
            LDSM_X4(b[0][0], b[0][1], b[1][0], b[1][1], bStage + kb);
            LDSM_X4(b[2][0], b[2][1], b[3][0], b[3][1],
                    bStage + (uint32_t)(16 * LDB * 2) + kb);
            #pragma unroll
            for (int mf = 0; mf < 2; mf++)
                #pragma unroll
                for (int nf = 0; nf < 4; nf++)
                    MMA16816(acc[mf][nf], a[mf], b[nf]);
        }

        if (kc == 1) {
            // ---- register epilogue for v-tile [v0, v0+128) ----
            const int rbase = wm * 32 + lg;
            #pragma unroll
            for (int mf = 0; mf < 2; mf++) {
                #pragma unroll
                for (int hh = 0; hh < 2; hh++) {
                    const int row = rbase + mf * 16 + hh * 8;
                    const float mx = MCOEF * XN[row];
                    float lowmax = -FLT_MAX;
                    #pragma unroll
                    for (int nf = 0; nf < 4; nf++) {
                        const int col = wn * 32 + nf * 8 + lq * 2;
                        float2 hn2 = *reinterpret_cast<const float2*>(g_halfnorm + v0 + col);
                        float2 en2 = *reinterpret_cast<const float2*>(g_enorm + v0 + col);
                        float s0 = acc[mf][nf][2 * hh]     - hn2.x;
                        float s1 = acc[mf][nf][2 * hh + 1] - hn2.y;
                        float me0 = fmaf(mx, en2.x, SLK);
                        float me1 = fmaf(mx, en2.y, SLK);
                        lowmax = fmaxf(lowmax, fmaxf(s0 - me0, s1 - me1));
                        acc[mf][nf][2 * hh]     = s0 + me0;   // upper bound
                        acc[mf][nf][2 * hh + 1] = s1 + me1;
                    }
                    atomicMax(&ML[row], fmap(lowmax));
                    // stale-lower threshold is always a valid lower bound ->
                    // candidate set stays a superset of the true argmax
                    const unsigned thr = ML[row];
                    #pragma unroll
                    for (int nf = 0; nf < 4; nf++) {
                        const int col = v0 + wn * 32 + nf * 8 + lq * 2;
                        if (fmap(acc[mf][nf][2 * hh]) >= thr) {
                            int p = atomicAdd(&CNT[row], 1);
                            if (p < CAP) CAND[row * CAP + p] = (unsigned short)col;
                        }
                        if (fmap(acc[mf][nf][2 * hh + 1]) >= thr) {
                            int p = atomicAdd(&CNT[row], 1);
                            if (p < CAP) CAND[row * CAP + p] = (unsigned short)(col + 1);
                        }
                    }
                }
            }
        }
        // separate this iteration's B-stage reads from the next prefetch writes
        __syncthreads();
    }

    // ---- exact fp32 rescore of candidates (warp per row) ----
    int* IDX = reinterpret_cast<int*>(smem + OFF_ML);   // reuse ML storage
    for (int rr = 0; rr < 8; rr++) {
        const int row = rr * 8 + w;
        const int r = m0 + row;
        float xr[8];
        const float* xp = g_hflat + (size_t)r * C_DIM;
        #pragma unroll
        for (int i = 0; i < 8; i++) xr[i] = xp[lane + i * 32];

        const int n = CNT[row];
        const bool full = (n > CAP);
        const int total = full ? VOCAB : n;

        float best = -FLT_MAX;
        int bidx = VOCAB;
        for (int j = 0; j < total; j++) {
            const int v = full ? j : (int)CAND[row * CAP + j];
            const float* ev = emb + (size_t)v * C_DIM;
            float p = 0.f;
            #pragma unroll
            for (int i = 0; i < 8; i++) p = fmaf(xr[i], __ldg(&ev[lane + i * 32]), p);
            #pragma unroll
            for (int o = 16; o > 0; o >>= 1) p += __shfl_xor_sync(0xFFFFFFFFu, p, o);
            const float s = p - __ldg(&g_halfnorm[v]);
            if (s > best || (s == best && v < bidx)) { best = s; bidx = v; }
        }
        if (lane == 0) {
            g_bestscore[r] = best;
            IDX[row] = bidx;               // overwrite ML slot (done with it)
        }
    }
    __syncthreads();

    // ---- fused tail: indices + z_q gather for this CTA's 64 rows ----
    // rows are n = m0..m0+63; same batch b (64 | 1024), sp = n & 1023.
    const int bb  = m0 >> 10;
    const int sp0 = m0 & 1023;
    if (tid < 64)
        out[4194304 + m0 + tid] = (float)IDX[tid];

    {
        const int sp = tid & 63;       // spatial offset within the 64-row strip
        const int cg = tid >> 6;       // channel group 0..3 (64 channels each)
        const int myidx = IDX[sp];
        const float* erow = emb + (size_t)myidx * C_DIM + cg * 64;
        float* obase = out + ((size_t)(bb * 256 + cg * 64) * 1024) + sp0 + sp;
        #pragma unroll 8
        for (int j = 0; j < 64; j++)
            obase[(size_t)j * 1024] = __ldg(&erow[j]);
    }
}

// ---------------------------------------------------------------------------
__global__ void loss_kernel(float* __restrict__ out) {
    __shared__ float sm[256];
    int t = threadIdx.x;
    float s1 = 0.f, s2 = 0.f;
    for (int i = t; i < 4096; i += 256)  s1 += g_partial[i];
    for (int i = t; i < N_VEC; i += 256) s2 += g_bestscore[i];
    sm[t] = s1 - 2.f * s2;
    __syncthreads();
    #pragma unroll
    for (int o = 128; o > 0; o >>= 1) {
        if (t < o) sm[t] += sm[t + o];
        __syncthreads();
    }
    if (t == 0) out[4210688] = sm[0] / 4194304.f;
}

// ---------------------------------------------------------------------------
extern "C" void kernel_launch(void* const* d_in, const int* in_sizes, int n_in,
                              void* d_out, int out_size) {
    const float* h   = (const float*)d_in[0];
    const float* emb = (const float*)d_in[1];
    float* out = (float*)d_out;

    static bool attr_set = false;
    if (!attr_set) {
        cudaFuncSetAttribute(pass1_kernel,
                             cudaFuncAttributeMaxDynamicSharedMemorySize, SMEM_P1);
        attr_set = true;
    }

    dim3 tgrid(32, 8, 16), tblk(32, 8);
    prep_h_kernel<<<tgrid, tblk>>>(h);
    prep_emb_kernel<<<VOCAB, 256>>>(emb);
    xnorm_kernel<<<N_VEC / 8, 256>>>();

    pass1_kernel<<<N_VEC / MTILE, 256, SMEM_P1>>>(emb, out);

    loss_kernel<<<1, 256>>>(out);
}

// round 17
// speedup vs baseline: 1.9914x; 1.0857x over previous
#include <cuda_runtime.h>
#include <cuda_fp16.h>
#include <cstdint>
#include <cfloat>

#define N_VEC  16384
#define VOCAB  4096
#define C_DIM  256

// rigorous fp16-quantization margin: |s_hat - s_exact| <= MCOEF*||x||*||e|| + SLK
#define MCOEF  1.06e-3f
#define SLK    0.05f

// ---------------------------------------------------------------------------
__device__ float  g_hflat[N_VEC * C_DIM];     // h transposed (N,C) fp32
__device__ __half g_A16[N_VEC * C_DIM];       // fp16 copy
__device__ __half g_B16[VOCAB * C_DIM];       // fp16 codebook
__device__ float  g_halfnorm[VOCAB];          // 0.5*||e||^2
__device__ float  g_enorm[VOCAB];             // ||e||
__device__ float  g_bestscore[N_VEC];
__device__ float  g_partial[4096];

// ---------------------------------------------------------------------------
__device__ __forceinline__ uint32_t smem_u32(const void* p) {
    uint32_t a;
    asm("{ .reg .u64 t; cvta.to.shared.u64 t, %1; cvt.u32.u64 %0, t; }"
        : "=r"(a) : "l"(p));
    return a;
}
__device__ __forceinline__ unsigned fmap(float f) {
    unsigned u = __float_as_uint(f);
    return u ^ ((unsigned)((int)u >> 31) | 0x80000000u);
}
#define CP_ASYNC16(saddr, gptr) \
    asm volatile("cp.async.cg.shared.global [%0], [%1], 16;" \
                 :: "r"(saddr), "l"(gptr) : "memory")
#define CP_COMMIT() asm volatile("cp.async.commit_group;" ::: "memory")
#define CP_WAIT1()  asm volatile("cp.async.wait_group 1;" ::: "memory")
#define CP_WAIT0()  asm volatile("cp.async.wait_group 0;" ::: "memory")

#define MMA16816(c, a, b) \
    asm volatile( \
        "mma.sync.aligned.m16n8k16.row.col.f32.f16.f16.f32 " \
        "{%0,%1,%2,%3}, {%4,%5,%6,%7}, {%8,%9}, {%0,%1,%2,%3};" \
        : "+f"((c)[0]), "+f"((c)[1]), "+f"((c)[2]), "+f"((c)[3]) \
        : "r"((a)[0]), "r"((a)[1]), "r"((a)[2]), "r"((a)[3]), \
          "r"((b)[0]), "r"((b)[1]))

#define LDSM_X4(r0, r1, r2, r3, addr) \
    asm volatile("ldmatrix.sync.aligned.m8n8.x4.shared.b16 {%0,%1,%2,%3}, [%4];" \
                 : "=r"(r0), "=r"(r1), "=r"(r2), "=r"(r3) : "r"(addr))

// ---------------------------------------------------------------------------
// merged prep: blocks [0,4096) transpose h (+fp16, +sumsq partial);
//              blocks [4096,8192) quantize embedding (+norms).
__global__ void prep_kernel(const float* __restrict__ h,
                            const float* __restrict__ emb) {
    __shared__ float tile[32][33];
    __shared__ float rsm[8];
    const int bid = blockIdx.x;
    const int t = threadIdx.x;

    if (bid < 4096) {
        int st = bid & 31, ct = (bid >> 5) & 7, b = bid >> 8;
        int c0 = ct * 32, s0 = st * 32;
        int tx = t & 31, ty = t >> 5;

        const float* src = h + ((size_t)b * C_DIM + c0) * 1024 + s0;
        float sq = 0.f;
        #pragma unroll
        for (int i = 0; i < 32; i += 8) {
            float v = src[(size_t)(ty + i) * 1024 + tx];
            tile[ty + i][tx] = v;
            sq = fmaf(v, v, sq);
        }
        __syncthreads();
        size_t rowbase = (size_t)b * 1024 + s0;
        #pragma unroll
        for (int i = 0; i < 32; i += 8) {
            float x = tile[tx][ty + i];
            size_t idx = (rowbase + ty + i) * C_DIM + c0 + tx;
            g_hflat[idx] = x;
            g_A16[idx]   = __float2half_rn(x);
        }
        #pragma unroll
        for (int o = 16; o > 0; o >>= 1) sq += __shfl_down_sync(0xFFFFFFFFu, sq, o);
        if ((t & 31) == 0) rsm[t >> 5] = sq;
        __syncthreads();
        if (t == 0) {
            float tot = 0.f;
            #pragma unroll
            for (int i = 0; i < 8; i++) tot += rsm[i];
            g_partial[bid] = tot;
        }
    } else {
        int v = bid - 4096;
        float x = emb[v * C_DIM + t];
        g_B16[v * C_DIM + t] = __float2half_rn(x);

        float s = x * x;
        #pragma unroll
        for (int o = 16; o > 0; o >>= 1) s += __shfl_down_sync(0xFFFFFFFFu, s, o);
        if ((t & 31) == 0) rsm[t >> 5] = s;
        __syncthreads();
        if (t == 0) {
            float tot = 0.f;
            #pragma unroll
            for (int i = 0; i < 8; i++) tot += rsm[i];
            g_halfnorm[v] = 0.5f * tot;
            g_enorm[v]    = sqrtf(tot);
        }
    }
}

// ---------------------------------------------------------------------------
// Fused mma.sync GEMM (R8 mainloop) + register filter + exact rescore +
// coalesced smem-staged z_q gather + indices; row norms computed in-kernel.
// 256 CTAs (M tile 64) x 256 threads (8 warps: wm in {0,1} x wn in {0..3}).
// Warp tile 32x32. v-tile N=128, K chunks of 128 (2 per v-tile).
#define MTILE 64
#define LDA   264        // halfs: row stride 528B == 16 mod 128 -> LDSM conflict-free
#define LDB   136        // halfs: row stride 272B == 16 mod 128 -> LDSM conflict-free
#define CAP   32
#define OFF_A    0                        // 64*264*2   = 33792
#define OFF_B    33792                    // 2*128*136*2= 69632 (reused as gather stage)
#define OFF_XN   103424                   // 64 floats
#define OFF_ML   103680                   // 64 u32 (reused as IDX after rescore)
#define OFF_CNT  103936                   // 64 ints
#define OFF_CAND 104192                   // 64*32 u16  = 4096
#define SMEM_P1  108288
#define STRIDE_ST 260                     // gather stage stride (floats); 64*260*4 <= 69632

__global__ __launch_bounds__(256, 2) void pass1_kernel(const float* __restrict__ emb,
                                                       float* __restrict__ out) {
    extern __shared__ char smem[];
    const uint32_t sb = smem_u32(smem);
    float*    XN  = reinterpret_cast<float*>(smem + OFF_XN);
    unsigned* ML  = reinterpret_cast<unsigned*>(smem + OFF_ML);
    int*      CNT = reinterpret_cast<int*>(smem + OFF_CNT);
    unsigned short* CAND = reinterpret_cast<unsigned short*>(smem + OFF_CAND);

    const int tid = threadIdx.x;
    const int w = tid >> 5, lane = tid & 31;
    const int wm = w & 1, wn = w >> 1;
    const int m0 = blockIdx.x * MTILE;
    const int lg = lane >> 2;        // group id 0..7
    const int lq = lane & 3;         // quad id 0..3

    if (tid < 64) {
        ML[tid] = 0u;                 // maps to "below -inf"
        CNT[tid] = 0;
    }

    // ldmatrix lane-address offsets (bytes)
    const uint32_t aLane = (uint32_t)(((lane & 15) * LDA + (lane >> 4) * 8) * 2);
    const uint32_t aBase0 = sb + OFF_A + (uint32_t)(wm * 32 * LDA * 2) + aLane;
    const uint32_t bLane = (uint32_t)(
        ((((lane & 7) | ((lane >> 4) << 3)) * LDB) + ((lane >> 3) & 1) * 8) * 2);

    // loader constants
    const int ldr = tid >> 4, ldq = tid & 15;          // B tile: 16 rows/iter
    const int lar = tid >> 5, laq = tid & 31;          // A tile: 8 rows/iter

    // resident A tile: 64 rows x 512B
    #pragma unroll
    for (int i = 0; i < 8; i++) {
        int r = lar + i * 8;
        CP_ASYNC16(sb + OFF_A + (uint32_t)(r * LDA * 2 + laq * 16),
                   g_A16 + (size_t)(m0 + r) * C_DIM + laq * 8);
    }
    CP_COMMIT();
    // B chunk 0 into stage 0 (128 rows x 256B)
    #pragma unroll
    for (int i = 0; i < 8; i++) {
        int r = ldr + i * 16;
        CP_ASYNC16(sb + OFF_B + (uint32_t)(r * LDB * 2 + ldq * 16),
                   g_B16 + (size_t)r * C_DIM + ldq * 8);
    }
    CP_COMMIT();

    // ---- row margin coefficients (overlaps the async copies above) ----
    // warp w computes rows w*8..w*8+7; visible to all after the first
    // mainloop __syncthreads (first use is the gc=1 epilogue).
    for (int rr = 0; rr < 8; rr++) {
        const int row = w * 8 + rr;
        const float* xp = g_hflat + (size_t)(m0 + row) * C_DIM;
        float p = 0.f;
        #pragma unroll
        for (int i = 0; i < 8; i++) { float x = xp[lane + i * 32]; p = fmaf(x, x, p); }
        #pragma unroll
        for (int o = 16; o > 0; o >>= 1) p += __shfl_xor_sync(0xFFFFFFFFu, p, o);
        if (lane == 0) XN[row] = MCOEF * sqrtf(p);
    }

    float acc[2][4][4];

    for (int gc = 0; gc < 64; gc++) {
        const int kc = gc & 1;
        const int v0 = (gc >> 1) << 7;

        // prefetch next chunk into the other stage (end-of-loop barrier
        // separates the reads of the stage being overwritten)
        if (gc < 63) {
            const int ng = gc + 1;
            const int nv0 = (ng >> 1) << 7;
            const int nk0 = (ng & 1) * 128;
            const uint32_t dstb = sb + OFF_B + (uint32_t)((ng & 1) * (128 * LDB * 2));
            #pragma unroll
            for (int i = 0; i < 8; i++) {
                int r = ldr + i * 16;
                CP_ASYNC16(dstb + (uint32_t)(r * LDB * 2 + ldq * 16),
                           g_B16 + (size_t)(nv0 + r) * C_DIM + nk0 + ldq * 8);
            }
            CP_COMMIT();
            CP_WAIT1();
        } else {
            CP_WAIT0();
        }
        __syncthreads();

        if (kc == 0) {
            #pragma unroll
            for (int mf = 0; mf < 2; mf++)
                #pragma unroll
                for (int nf = 0; nf < 4; nf++)
                    #pragma unroll
                    for (int i = 0; i < 4; i++) acc[mf][nf][i] = 0.f;
        }

        const uint32_t bStage = sb + OFF_B + (uint32_t)((gc & 1) * (128 * LDB * 2))
                              + (uint32_t)(wn * 32 * LDB * 2) + bLane;
        const uint32_t aK = (uint32_t)(kc * 128 * 2);

        #pragma unroll
        for (int ks = 0; ks < 8; ks++) {
            uint32_t a[2][4], b[4][2];
            const uint32_t ka = aK + (uint32_t)(ks * 32);    // ks*16 halfs
            const uint32_t kb = (uint32_t)(ks * 32);
            LDSM_X4(a[0][0], a[0][1], a[0][2], a[0][3], aBase0 + ka);
            LDSM_X4(a[1][0], a[1][1], a[1][2], a[1][3],
                    aBase0 + (uint32_t)(16 * LDA * 2) + ka);
            LDSM_X4(b[0][0], b[0][1], b[1][0], b[1][1], bStage + kb);
            LDSM_X4(b[2][0], b[2][1], b[3][0], b[3][1],
                    bStage + (uint32_t)(16 * LDB * 2) + kb);
            #pragma unroll
            for (int mf = 0; mf < 2; mf++)
                #pragma unroll
                for (int nf = 0; nf < 4; nf++)
                    MMA16816(acc[mf][nf], a[mf], b[nf]);
        }

        if (kc == 1) {
            // ---- register epilogue for v-tile [v0, v0+128) ----
            const int rbase = wm * 32 + lg;
            #pragma unroll
            for (int mf = 0; mf < 2; mf++) {
                #pragma unroll
                for (int hh = 0; hh < 2; hh++) {
                    const int row = rbase + mf * 16 + hh * 8;
                    const float mx = XN[row];
                    float lowmax = -FLT_MAX;
                    #pragma unroll
                    for (int nf = 0; nf < 4; nf++) {
                        const int col = wn * 32 + nf * 8 + lq * 2;
                        float2 hn2 = *reinterpret_cast<const float2*>(g_halfnorm + v0 + col);
                        float2 en2 = *reinterpret_cast<const float2*>(g_enorm + v0 + col);
                        float s0 = acc[mf][nf][2 * hh]     - hn2.x;
                        float s1 = acc[mf][nf][2 * hh + 1] - hn2.y;
                        float me0 = fmaf(mx, en2.x, SLK);
                        float me1 = fmaf(mx, en2.y, SLK);
                        lowmax = fmaxf(lowmax, fmaxf(s0 - me0, s1 - me1));
                        acc[mf][nf][2 * hh]     = s0 + me0;   // upper bound
                        acc[mf][nf][2 * hh + 1] = s1 + me1;
                    }
                    atomicMax(&ML[row], fmap(lowmax));
                    // stale-lower threshold is always a valid lower bound ->
                    // candidate set stays a superset of the true argmax
                    const unsigned thr = ML[row];
                    #pragma unroll
                    for (int nf = 0; nf < 4; nf++) {
                        const int col = v0 + wn * 32 + nf * 8 + lq * 2;
                        if (fmap(acc[mf][nf][2 * hh]) >= thr) {
                            int p = atomicAdd(&CNT[row], 1);
                            if (p < CAP) CAND[row * CAP + p] = (unsigned short)col;
                        }
                        if (fmap(acc[mf][nf][2 * hh + 1]) >= thr) {
                            int p = atomicAdd(&CNT[row], 1);
                            if (p < CAP) CAND[row * CAP + p] = (unsigned short)(col + 1);
                        }
                    }
                }
            }
        }
        // separate this iteration's B-stage reads from the next prefetch writes
        __syncthreads();
    }

    // ---- exact fp32 rescore of candidates (warp per row) ----
    int* IDX = reinterpret_cast<int*>(smem + OFF_ML);   // reuse ML storage
    for (int rr = 0; rr < 8; rr++) {
        const int row = rr * 8 + w;
        const int r = m0 + row;
        float xr[8];
        const float* xp = g_hflat + (size_t)r * C_DIM;
        #pragma unroll
        for (int i = 0; i < 8; i++) xr[i] = xp[lane + i * 32];

        const int n = CNT[row];
        const bool full = (n > CAP);
        const int total = full ? VOCAB : n;

        float best = -FLT_MAX;
        int bidx = VOCAB;
        for (int j = 0; j < total; j++) {
            const int v = full ? j : (int)CAND[row * CAP + j];
            const float* ev = emb + (size_t)v * C_DIM;
            float p = 0.f;
            #pragma unroll
            for (int i = 0; i < 8; i++) p = fmaf(xr[i], __ldg(&ev[lane + i * 32]), p);
            #pragma unroll
            for (int o = 16; o > 0; o >>= 1) p += __shfl_xor_sync(0xFFFFFFFFu, p, o);
            const float s = p - __ldg(&g_halfnorm[v]);
            if (s > best || (s == best && v < bidx)) { best = s; bidx = v; }
        }
        if (lane == 0) {
            g_bestscore[r] = best;
            IDX[row] = bidx;               // overwrite ML slot (done with it)
        }
    }
    __syncthreads();

    // ---- fused tail: indices + coalesced smem-staged z_q gather ----
    const int bb  = m0 >> 10;
    const int sp0 = m0 & 1023;
    if (tid < 64)
        out[4194304 + m0 + tid] = (float)IDX[tid];

    // stage the 64 selected codebook rows into smem (coalesced 512B reads);
    // reuses the B-stage region (mainloop done).
    float* ST = reinterpret_cast<float*>(smem + OFF_B);
    for (int rr = 0; rr < 8; rr++) {
        const int sp = w * 8 + rr;
        const float4* src = reinterpret_cast<const float4*>(
            emb + (size_t)IDX[sp] * C_DIM);
        float4 v0 = __ldg(&src[lane]);
        float4 v1 = __ldg(&src[lane + 32]);
        float* dst = ST + sp * STRIDE_ST;
        *reinterpret_cast<float4*>(dst + lane * 4)       = v0;
        *reinterpret_cast<float4*>(dst + lane * 4 + 128) = v1;
    }
    __syncthreads();

    // coalesced writes: for each channel, 64 consecutive sp floats
    {
        const int sp = tid & 63;
        const int cg = tid >> 6;       // channel group 0..3
        const float* srow = ST + sp * STRIDE_ST + cg * 64;
        float* obase = out + ((size_t)(bb * 256 + cg * 64) * 1024) + sp0 + sp;
        #pragma unroll 8
        for (int j = 0; j < 64; j++)
            obase[(size_t)j * 1024] = srow[j];
    }
}

// ---------------------------------------------------------------------------
__global__ void loss_kernel(float* __restrict__ out) {
    __shared__ float sm[256];
    int t = threadIdx.x;
    float s1 = 0.f, s2 = 0.f;
    for (int i = t; i < 4096; i += 256)  s1 += g_partial[i];
    for (int i = t; i < N_VEC; i += 256) s2 += g_bestscore[i];
    sm[t] = s1 - 2.f * s2;
    __syncthreads();
    #pragma unroll
    for (int o = 128; o > 0; o >>= 1) {
        if (t < o) sm[t] += sm[t + o];
        __syncthreads();
    }
    if (t == 0) out[4210688] = sm[0] / 4194304.f;
}

// ---------------------------------------------------------------------------
extern "C" void kernel_launch(void* const* d_in, const int* in_sizes, int n_in,
                              void* d_out, int out_size) {
    const float* h   = (const float*)d_in[0];
    const float* emb = (const float*)d_in[1];
    float* out = (float*)d_out;

    static bool attr_set = false;
    if (!attr_set) {
        cudaFuncSetAttribute(pass1_kernel,
                             cudaFuncAttributeMaxDynamicSharedMemorySize, SMEM_P1);
        attr_set = true;
    }

    prep_kernel<<<8192, 256>>>(h, emb);

    pass1_kernel<<<N_VEC / MTILE, 256, SMEM_P1>>>(emb, out);

    loss_kernel<<<1, 256>>>(out);
}